// round 14
// baseline (speedup 1.0000x reference)
#include <cuda_runtime.h>
#include <math.h>

#define DT 0.05f
#define NSTEPS 4
#define NTHREADS 128
#define PTS 16          // points per block (8 threads each)
#define TSTR 20         // tile row stride (floats): conflict-free, 16B aligned
#define PPB 836         // tile 320 + Ws 256 + Fs 256 + pad (mod 32 == 4)
#define TILE_OFF 0
#define W_OFF 320       // W stash (own rows)
#define F_OFF 576       // S0 initially, then F accumulator
#define SMEM_BYTES (PTS * PPB * 4)

typedef unsigned long long u64;

__device__ __forceinline__ u64 pack2(float x, float y) {
    u64 r;
    asm("mov.b64 %0, {%1, %2};" : "=l"(r) : "f"(x), "f"(y));
    return r;
}
__device__ __forceinline__ void unpack2(u64 v, float& x, float& y) {
    asm("mov.b64 {%0, %1}, %2;" : "=f"(x), "=f"(y) : "l"(v));
}
__device__ __forceinline__ void fma2(u64& d, u64 a, u64 b) {
    asm("fma.rn.f32x2 %0, %1, %2, %0;" : "+l"(d) : "l"(a), "l"(b));
}

__device__ __forceinline__ void put2(float* tile, int q, const float v0[16],
                                     const float v1[16]) {
    __syncwarp();
    float4* d0 = (float4*)(tile + q * TSTR);
    float4* d1 = (float4*)(tile + (q + 8) * TSTR);
    d0[0] = make_float4(v0[0], v0[1], v0[2], v0[3]);
    d0[1] = make_float4(v0[4], v0[5], v0[6], v0[7]);
    d0[2] = make_float4(v0[8], v0[9], v0[10], v0[11]);
    d0[3] = make_float4(v0[12], v0[13], v0[14], v0[15]);
    d1[0] = make_float4(v1[0], v1[1], v1[2], v1[3]);
    d1[1] = make_float4(v1[4], v1[5], v1[6], v1[7]);
    d1[2] = make_float4(v1[8], v1[9], v1[10], v1[11]);
    d1[3] = make_float4(v1[12], v1[13], v1[14], v1[15]);
    __syncwarp();
}

// c{0,1} = a{0,1} * B. c, a distinct arrays.
template <int BSTR>
__device__ __forceinline__ void mm2z(float c0[16], float c1[16],
                                     const float a0[16], const float a1[16],
                                     const float* Bs) {
    u64 acc0[8], acc1[8];
#pragma unroll
    for (int i = 0; i < 8; i++) { acc0[i] = 0ULL; acc1[i] = 0ULL; }
#pragma unroll
    for (int k = 0; k < 16; k++) {
        const ulonglong2* bp = (const ulonglong2*)(Bs + k * BSTR);
        ulonglong2 ba = bp[0], bb = bp[1], bc = bp[2], bd = bp[3];
        u64 ak0 = pack2(a0[k], a0[k]);
        u64 ak1 = pack2(a1[k], a1[k]);
        fma2(acc0[0], ak0, ba.x); fma2(acc0[1], ak0, ba.y);
        fma2(acc0[2], ak0, bb.x); fma2(acc0[3], ak0, bb.y);
        fma2(acc0[4], ak0, bc.x); fma2(acc0[5], ak0, bc.y);
        fma2(acc0[6], ak0, bd.x); fma2(acc0[7], ak0, bd.y);
        fma2(acc1[0], ak1, ba.x); fma2(acc1[1], ak1, ba.y);
        fma2(acc1[2], ak1, bb.x); fma2(acc1[3], ak1, bb.y);
        fma2(acc1[4], ak1, bc.x); fma2(acc1[5], ak1, bc.y);
        fma2(acc1[6], ak1, bd.x); fma2(acc1[7], ak1, bd.y);
    }
#pragma unroll
    for (int i = 0; i < 8; i++) {
        unpack2(acc0[i], c0[2 * i], c0[2 * i + 1]);
        unpack2(acc1[i], c1[2 * i], c1[2 * i + 1]);
    }
}

// c{0,1} += a{0,1} * B. c, a distinct arrays.
template <int BSTR>
__device__ __forceinline__ void mm2a(float c0[16], float c1[16],
                                     const float a0[16], const float a1[16],
                                     const float* Bs) {
    u64 acc0[8], acc1[8];
#pragma unroll
    for (int i = 0; i < 8; i++) {
        acc0[i] = pack2(c0[2 * i], c0[2 * i + 1]);
        acc1[i] = pack2(c1[2 * i], c1[2 * i + 1]);
    }
#pragma unroll
    for (int k = 0; k < 16; k++) {
        const ulonglong2* bp = (const ulonglong2*)(Bs + k * BSTR);
        ulonglong2 ba = bp[0], bb = bp[1], bc = bp[2], bd = bp[3];
        u64 ak0 = pack2(a0[k], a0[k]);
        u64 ak1 = pack2(a1[k], a1[k]);
        fma2(acc0[0], ak0, ba.x); fma2(acc0[1], ak0, ba.y);
        fma2(acc0[2], ak0, bb.x); fma2(acc0[3], ak0, bb.y);
        fma2(acc0[4], ak0, bc.x); fma2(acc0[5], ak0, bc.y);
        fma2(acc0[6], ak0, bd.x); fma2(acc0[7], ak0, bd.y);
        fma2(acc1[0], ak1, ba.x); fma2(acc1[1], ak1, ba.y);
        fma2(acc1[2], ak1, bb.x); fma2(acc1[3], ak1, bb.y);
        fma2(acc1[4], ak1, bc.x); fma2(acc1[5], ak1, bc.y);
        fma2(acc1[6], ak1, bd.x); fma2(acc1[7], ak1, bd.y);
    }
#pragma unroll
    for (int i = 0; i < 8; i++) {
        unpack2(acc0[i], c0[2 * i], c0[2 * i + 1]);
        unpack2(acc1[i], c1[2 * i], c1[2 * i + 1]);
    }
}

__device__ __forceinline__ void ld_row16(float v[16], const float* src) {
    const float4* s = (const float4*)src;
#pragma unroll
    for (int i = 0; i < 4; i++) {
        float4 t = s[i];
        v[4 * i + 0] = t.x; v[4 * i + 1] = t.y;
        v[4 * i + 2] = t.z; v[4 * i + 3] = t.w;
    }
}
__device__ __forceinline__ void st_row16(float* dst, const float v[16]) {
    float4* d = (float4*)dst;
    d[0] = make_float4(v[0], v[1], v[2], v[3]);
    d[1] = make_float4(v[4], v[5], v[6], v[7]);
    d[2] = make_float4(v[8], v[9], v[10], v[11]);
    d[3] = make_float4(v[12], v[13], v[14], v[15]);
}

// kick: W <- W - dt*W^2
#define KICK()                                                               \
    do {                                                                     \
        put2(tile, q, W0, W1);                                               \
        _Pragma("unroll")                                                    \
        for (int j = 0; j < 16; j++) { T0[j] = -DT * W0[j]; T1[j] = -DT * W1[j]; } \
        mm2a<TSTR>(W0, W1, T0, T1, tile);                                    \
    } while (0)

// E-section: entry: W regs = W, Ws = W (stashed). Exit: tile = E = exp(2dt*W)
// via (Taylor4(dt*W))^2. W regs consumed.
#define E_SECTION()                                                          \
    do {                                                                     \
        _Pragma("unroll")                                                    \
        for (int j = 0; j < 16; j++) { T0[j] = DT * W0[j]; T1[j] = DT * W1[j]; } \
        put2(tile, q, T0, T1);                   /* tile <- Y = dt*W */      \
        mm2z<TSTR>(G0, G1, T0, T1, tile);        /* G = Y^2 */               \
        _Pragma("unroll")                                                    \
        for (int j = 0; j < 16; j++) {                                       \
            T0[j] = fmaf(1.0f / 24.0f, G0[j], (1.0f / 6.0f) * T0[j]);        \
            T1[j] = fmaf(1.0f / 24.0f, G1[j], (1.0f / 6.0f) * T1[j]);        \
        }                                                                    \
        T0[q] += 0.5f; T1[r1] += 0.5f;                                       \
        put2(tile, q, T0, T1);                   /* tile <- U */             \
        ld_row16(T0, Ws + q * 16);               /* reload W (own rows) */   \
        ld_row16(T1, Ws + r1 * 16);                                          \
        _Pragma("unroll")                                                    \
        for (int j = 0; j < 16; j++) { T0[j] *= DT; T1[j] *= DT; }           \
        T0[q] += 1.0f; T1[r1] += 1.0f;           /* T = I + dt*W */          \
        mm2a<TSTR>(T0, T1, G0, G1, tile);        /* T = E4 */                \
        put2(tile, q, T0, T1);                   /* tile <- E4 */            \
        mm2z<TSTR>(G0, G1, T0, T1, tile);        /* G = E4^2 = E */          \
        put2(tile, q, G0, G1);                   /* tile <- E */             \
    } while (0)

__global__ void __launch_bounds__(NTHREADS, 3)
ham_kernel(const float* __restrict__ mu, const float* __restrict__ Sigma,
           const float* __restrict__ phi, const float* __restrict__ pi_mu,
           const float* __restrict__ pi_Sigma, const float* __restrict__ pi_phi,
           const float* __restrict__ M_inv,
           float* __restrict__ mu_o, float* __restrict__ Sig_o,
           float* __restrict__ phi_o) {
    extern __shared__ float smem[];
    const int tid = threadIdx.x;
    const int lp = tid >> 3;   // local point 0..15
    const int q = tid & 7;     // owns rows q and q+8
    const int r1 = q + 8;
    const int p = blockIdx.x * PTS + lp;
    float* tile = smem + lp * PPB + TILE_OFF;
    float* Ws = smem + lp * PPB + W_OFF;   // stride 16
    float* Fs = smem + lp * PPB + F_OFF;   // stride 16

    float W0[16], W1[16], T0[16], T1[16], G0[16], G1[16];

    // ---- S0 -> Fs (temporary home); P -> T ----
    ld_row16(T0, Sigma + (size_t)p * 256 + q * 16);
    ld_row16(T1, Sigma + (size_t)p * 256 + r1 * 16);
    st_row16(Fs + q * 16, T0);
    st_row16(Fs + r1 * 16, T1);
    ld_row16(T0, pi_Sigma + (size_t)p * 256 + q * 16);
    ld_row16(T1, pi_Sigma + (size_t)p * 256 + r1 * 16);

    // ---- mu update: mu + NSTEPS*dt * M_inv @ pi_mu ----
    {
        float pmv[16];
        ld_row16(pmv, pi_mu + (size_t)p * 16);
        const float* M0 = M_inv + (size_t)p * 256 + q * 16;
        const float* M1 = M_inv + (size_t)p * 256 + r1 * 16;
        float s0 = 0.0f, s1 = 0.0f;
#pragma unroll
        for (int j = 0; j < 16; j++) {
            s0 = fmaf(M0[j], pmv[j], s0);
            s1 = fmaf(M1[j], pmv[j], s1);
        }
        mu_o[(size_t)p * 16 + q]  = mu[(size_t)p * 16 + q]  + ((float)NSTEPS * DT) * s0;
        mu_o[(size_t)p * 16 + r1] = mu[(size_t)p * 16 + r1] + ((float)NSTEPS * DT) * s1;
    }

    // ---- phi update (thread q==0 of each point) ----
    if (q == 0) {
        float px = phi[p * 3 + 0], py = phi[p * 3 + 1], pz = phi[p * 3 + 2];
        const float vx = pi_phi[p * 3 + 0];
        const float vy = pi_phi[p * 3 + 1];
        const float vz = pi_phi[p * 3 + 2];
        const float TWO_PI = 6.283185307179586f;
        const float PI_F = 3.141592653589793f;
        const float R_MAX = 3.131592653589793f;
#pragma unroll 1
        for (int s = 0; s < NSTEPS; s++) {
            px += DT * vx; py += DT * vy; pz += DT * vz;
            float th = sqrtf(px * px + py * py + pz * pz);
            float ths = fmaxf(th, 1e-12f);
            float inv = 1.0f / ths;
            float ax = px * inv, ay = py * inv, az = pz * inv;
            float tw = fmodf(th, TWO_PI);
            bool flip = tw > PI_F;
            float tf = flip ? (TWO_PI - tw) : tw;
            if (flip) { ax = -ax; ay = -ay; az = -az; }
            tf = fminf(tf, R_MAX);
            px = ax * tf; py = ay * tf; pz = az * tf;
        }
        phi_o[p * 3 + 0] = px;
        phi_o[p * 3 + 1] = py;
        phi_o[p * 3 + 2] = pz;
    }
    __syncwarp();  // S0 (in Fs) visible to all threads of the point

    // ===== peel step 0 =====
    mm2z<16>(W0, W1, T0, T1, Fs);                // W = P * S0
    KICK();                                      // kick1
    st_row16(Ws + q * 16, W0);                   // stash W (own rows)
    st_row16(Ws + r1 * 16, W1);
    E_SECTION();                                 // tile = E0
    st_row16(Fs + q * 16, G0);                   // F := E0 (own rows)
    st_row16(Fs + r1 * 16, G1);

    // ===== steps 1..3: uniform, branch-free =====
#pragma unroll 1
    for (int step = 1; step < NSTEPS; step++) {
        ld_row16(T0, Ws + q * 16);               // W_old
        ld_row16(T1, Ws + r1 * 16);
        mm2z<TSTR>(W0, W1, T0, T1, tile);        // W <- W_old * E_prev
        KICK();                                  // kick2 of prev step
        KICK();                                  // kick1 of this step
        st_row16(Ws + q * 16, W0);               // stash W
        st_row16(Ws + r1 * 16, W1);
        E_SECTION();                             // tile = E_step
        ld_row16(T0, Fs + q * 16);               // F
        ld_row16(T1, Fs + r1 * 16);
        mm2z<TSTR>(G0, G1, T0, T1, tile);        // F <- F * E_step
        st_row16(Fs + q * 16, G0);
        st_row16(Fs + r1 * 16, G1);
    }

    // ===== final: S_out = sym(S0 * F) =====
    ld_row16(T0, Sigma + (size_t)p * 256 + q * 16);   // S0 rows (L2)
    ld_row16(T1, Sigma + (size_t)p * 256 + r1 * 16);
    __syncwarp();                                // all F rows written
    mm2z<16>(W0, W1, T0, T1, Fs);                // W = S0 * F
    put2(tile, q, W0, W1);                       // tile <- S_new (transpose)
#pragma unroll
    for (int j = 0; j < 16; j++) {
        W0[j] = 0.5f * (W0[j] + tile[j * TSTR + q]);
        W1[j] = 0.5f * (W1[j] + tile[j * TSTR + r1]);
    }
    st_row16(Sig_o + (size_t)p * 256 + q * 16, W0);
    st_row16(Sig_o + (size_t)p * 256 + r1 * 16, W1);
}

extern "C" void kernel_launch(void* const* d_in, const int* in_sizes, int n_in,
                              void* d_out, int out_size) {
    const float* mu       = (const float*)d_in[0];
    const float* Sigma    = (const float*)d_in[1];
    const float* phi      = (const float*)d_in[2];
    const float* pi_mu    = (const float*)d_in[3];
    const float* pi_Sigma = (const float*)d_in[4];
    const float* pi_phi   = (const float*)d_in[5];
    const float* M_inv    = (const float*)d_in[6];

    const int npts = in_sizes[0] / 16;  // B*N = 32768
    float* out = (float*)d_out;
    float* mu_o  = out;
    float* Sig_o = out + (size_t)npts * 16;
    float* phi_o = out + (size_t)npts * 16 + (size_t)npts * 256;

    cudaFuncSetAttribute(ham_kernel, cudaFuncAttributeMaxDynamicSharedMemorySize,
                         SMEM_BYTES);

    dim3 grid(npts / PTS);
    dim3 block(NTHREADS);
    ham_kernel<<<grid, block, SMEM_BYTES>>>(mu, Sigma, phi, pi_mu, pi_Sigma,
                                            pi_phi, M_inv, mu_o, Sig_o, phi_o);
}

// round 15
// speedup vs baseline: 1.0040x; 1.0040x over previous
#include <cuda_runtime.h>
#include <math.h>

#define DT 0.05f
#define NSTEPS 4
#define NTHREADS 128
#define PTS 32          // points per block (4 threads each, 8 points/warp)
#define TSTR 20         // tile row stride (floats)
#define PPB 836         // tile 320 + Ws 256 + Fs 256 + pad (mod 32 == 4)
#define TILE_OFF 0
#define W_OFF 320
#define F_OFF 576
#define SMEM_BYTES (PTS * PPB * 4)

typedef unsigned long long u64;

__device__ __forceinline__ u64 pack2(float x, float y) {
    u64 r;
    asm("mov.b64 %0, {%1, %2};" : "=l"(r) : "f"(x), "f"(y));
    return r;
}
__device__ __forceinline__ void unpack2(u64 v, float& x, float& y) {
    asm("mov.b64 {%0, %1}, %2;" : "=f"(x), "=f"(y) : "l"(v));
}
__device__ __forceinline__ void fma2(u64& d, u64 a, u64 b) {
    asm("fma.rn.f32x2 %0, %1, %2, %0;" : "+l"(d) : "l"(a), "l"(b));
}

// Thread owns rows q, q+4, q+8, q+12 of its point.
__device__ __forceinline__ void put4(float* tile, int q, const float v[4][16]) {
    __syncwarp();
#pragma unroll
    for (int r = 0; r < 4; r++) {
        float4* d = (float4*)(tile + (q + 4 * r) * TSTR);
        d[0] = make_float4(v[r][0], v[r][1], v[r][2], v[r][3]);
        d[1] = make_float4(v[r][4], v[r][5], v[r][6], v[r][7]);
        d[2] = make_float4(v[r][8], v[r][9], v[r][10], v[r][11]);
        d[3] = make_float4(v[r][12], v[r][13], v[r][14], v[r][15]);
    }
    __syncwarp();
}

// c = a * B  (zero-init). c, a distinct.
template <int BSTR>
__device__ __forceinline__ void mm4z(float c[4][16], const float a[4][16],
                                     const float* Bs) {
    u64 acc[4][8];
#pragma unroll
    for (int r = 0; r < 4; r++)
#pragma unroll
        for (int i = 0; i < 8; i++) acc[r][i] = 0ULL;
#pragma unroll
    for (int k = 0; k < 16; k++) {
        const ulonglong2* bp = (const ulonglong2*)(Bs + k * BSTR);
        ulonglong2 ba = bp[0], bb = bp[1], bc = bp[2], bd = bp[3];
#pragma unroll
        for (int r = 0; r < 4; r++) {
            u64 ak = pack2(a[r][k], a[r][k]);
            fma2(acc[r][0], ak, ba.x); fma2(acc[r][1], ak, ba.y);
            fma2(acc[r][2], ak, bb.x); fma2(acc[r][3], ak, bb.y);
            fma2(acc[r][4], ak, bc.x); fma2(acc[r][5], ak, bc.y);
            fma2(acc[r][6], ak, bd.x); fma2(acc[r][7], ak, bd.y);
        }
    }
#pragma unroll
    for (int r = 0; r < 4; r++)
#pragma unroll
        for (int i = 0; i < 8; i++)
            unpack2(acc[r][i], c[r][2 * i], c[r][2 * i + 1]);
}

// c += a * B. c, a distinct.
template <int BSTR>
__device__ __forceinline__ void mm4a(float c[4][16], const float a[4][16],
                                     const float* Bs) {
    u64 acc[4][8];
#pragma unroll
    for (int r = 0; r < 4; r++)
#pragma unroll
        for (int i = 0; i < 8; i++)
            acc[r][i] = pack2(c[r][2 * i], c[r][2 * i + 1]);
#pragma unroll
    for (int k = 0; k < 16; k++) {
        const ulonglong2* bp = (const ulonglong2*)(Bs + k * BSTR);
        ulonglong2 ba = bp[0], bb = bp[1], bc = bp[2], bd = bp[3];
#pragma unroll
        for (int r = 0; r < 4; r++) {
            u64 ak = pack2(a[r][k], a[r][k]);
            fma2(acc[r][0], ak, ba.x); fma2(acc[r][1], ak, ba.y);
            fma2(acc[r][2], ak, bb.x); fma2(acc[r][3], ak, bb.y);
            fma2(acc[r][4], ak, bc.x); fma2(acc[r][5], ak, bc.y);
            fma2(acc[r][6], ak, bd.x); fma2(acc[r][7], ak, bd.y);
        }
    }
#pragma unroll
    for (int r = 0; r < 4; r++)
#pragma unroll
        for (int i = 0; i < 8; i++)
            unpack2(acc[r][i], c[r][2 * i], c[r][2 * i + 1]);
}

__device__ __forceinline__ void ld_row16(float v[16], const float* src) {
    const float4* s = (const float4*)src;
#pragma unroll
    for (int i = 0; i < 4; i++) {
        float4 t = s[i];
        v[4 * i + 0] = t.x; v[4 * i + 1] = t.y;
        v[4 * i + 2] = t.z; v[4 * i + 3] = t.w;
    }
}
__device__ __forceinline__ void st_row16(float* dst, const float v[16]) {
    float4* d = (float4*)dst;
    d[0] = make_float4(v[0], v[1], v[2], v[3]);
    d[1] = make_float4(v[4], v[5], v[6], v[7]);
    d[2] = make_float4(v[8], v[9], v[10], v[11]);
    d[3] = make_float4(v[12], v[13], v[14], v[15]);
}

// own-row stash ld/st (stride 16)
__device__ __forceinline__ void ld4(float v[4][16], const float* s, int q) {
#pragma unroll
    for (int r = 0; r < 4; r++) ld_row16(v[r], s + (q + 4 * r) * 16);
}
__device__ __forceinline__ void st4(float* d, const float v[4][16], int q) {
#pragma unroll
    for (int r = 0; r < 4; r++) st_row16(d + (q + 4 * r) * 16, v[r]);
}

// kick: W <- W - dt*W^2
#define KICK()                                                               \
    do {                                                                     \
        put4(tile, q, W);                                                    \
        _Pragma("unroll")                                                    \
        for (int r = 0; r < 4; r++)                                          \
            _Pragma("unroll")                                                \
            for (int j = 0; j < 16; j++) T[r][j] = -DT * W[r][j];            \
        mm4a<TSTR>(W, T, tile);                                              \
    } while (0)

// E-section: entry: W regs = W, Ws = W (stashed). Exit: tile = exp(2dt*W)
// via (Taylor4(dt*W))^2. W regs consumed.
#define E_SECTION()                                                          \
    do {                                                                     \
        _Pragma("unroll")                                                    \
        for (int r = 0; r < 4; r++)                                          \
            _Pragma("unroll")                                                \
            for (int j = 0; j < 16; j++) T[r][j] = DT * W[r][j];             \
        put4(tile, q, T);                        /* tile <- Y = dt*W */      \
        mm4z<TSTR>(G, T, tile);                  /* G = Y^2 */               \
        _Pragma("unroll")                                                    \
        for (int r = 0; r < 4; r++) {                                        \
            _Pragma("unroll")                                                \
            for (int j = 0; j < 16; j++)                                     \
                T[r][j] = fmaf(1.0f / 24.0f, G[r][j], (1.0f / 6.0f) * T[r][j]); \
            T[r][q + 4 * r] += 0.5f;                                         \
        }                                                                    \
        put4(tile, q, T);                        /* tile <- U */             \
        ld4(T, Ws, q);                           /* reload W */              \
        _Pragma("unroll")                                                    \
        for (int r = 0; r < 4; r++) {                                        \
            _Pragma("unroll")                                                \
            for (int j = 0; j < 16; j++) T[r][j] *= DT;                      \
            T[r][q + 4 * r] += 1.0f;             /* T = I + dt*W */          \
        }                                                                    \
        mm4a<TSTR>(T, G, tile);                  /* T = E4 */                \
        put4(tile, q, T);                        /* tile <- E4 */            \
        mm4z<TSTR>(G, T, tile);                  /* G = E4^2 = E */          \
        put4(tile, q, G);                        /* tile <- E */             \
    } while (0)

__global__ void __launch_bounds__(NTHREADS, 2)
ham_kernel(const float* __restrict__ mu, const float* __restrict__ Sigma,
           const float* __restrict__ phi, const float* __restrict__ pi_mu,
           const float* __restrict__ pi_Sigma, const float* __restrict__ pi_phi,
           const float* __restrict__ M_inv,
           float* __restrict__ mu_o, float* __restrict__ Sig_o,
           float* __restrict__ phi_o) {
    extern __shared__ float smem[];
    const int tid = threadIdx.x;
    const int lp = tid >> 2;   // local point 0..31
    const int q = tid & 3;     // owns rows q, q+4, q+8, q+12
    const int p = blockIdx.x * PTS + lp;
    float* tile = smem + lp * PPB + TILE_OFF;
    float* Ws = smem + lp * PPB + W_OFF;   // stride 16
    float* Fs = smem + lp * PPB + F_OFF;   // stride 16

    float W[4][16], T[4][16], G[4][16];

    // ---- S0 -> Fs; P -> T ----
    {
#pragma unroll
        for (int r = 0; r < 4; r++)
            ld_row16(T[r], Sigma + (size_t)p * 256 + (q + 4 * r) * 16);
        st4(Fs, T, q);
#pragma unroll
        for (int r = 0; r < 4; r++)
            ld_row16(T[r], pi_Sigma + (size_t)p * 256 + (q + 4 * r) * 16);
    }

    // ---- mu update (4 rows): mu + NSTEPS*dt * M_inv @ pi_mu ----
    {
        float pmv[16];
        ld_row16(pmv, pi_mu + (size_t)p * 16);
#pragma unroll
        for (int r = 0; r < 4; r++) {
            const float* Mr = M_inv + (size_t)p * 256 + (q + 4 * r) * 16;
            float s = 0.0f;
#pragma unroll
            for (int j = 0; j < 16; j++) s = fmaf(Mr[j], pmv[j], s);
            mu_o[(size_t)p * 16 + q + 4 * r] =
                mu[(size_t)p * 16 + q + 4 * r] + ((float)NSTEPS * DT) * s;
        }
    }

    // ---- phi update (thread q==0 of each point) ----
    if (q == 0) {
        float px = phi[p * 3 + 0], py = phi[p * 3 + 1], pz = phi[p * 3 + 2];
        const float vx = pi_phi[p * 3 + 0];
        const float vy = pi_phi[p * 3 + 1];
        const float vz = pi_phi[p * 3 + 2];
        const float TWO_PI = 6.283185307179586f;
        const float PI_F = 3.141592653589793f;
        const float R_MAX = 3.131592653589793f;
#pragma unroll 1
        for (int s = 0; s < NSTEPS; s++) {
            px += DT * vx; py += DT * vy; pz += DT * vz;
            float th = sqrtf(px * px + py * py + pz * pz);
            float ths = fmaxf(th, 1e-12f);
            float inv = 1.0f / ths;
            float ax = px * inv, ay = py * inv, az = pz * inv;
            float tw = fmodf(th, TWO_PI);
            bool flip = tw > PI_F;
            float tf = flip ? (TWO_PI - tw) : tw;
            if (flip) { ax = -ax; ay = -ay; az = -az; }
            tf = fminf(tf, R_MAX);
            px = ax * tf; py = ay * tf; pz = az * tf;
        }
        phi_o[p * 3 + 0] = px;
        phi_o[p * 3 + 1] = py;
        phi_o[p * 3 + 2] = pz;
    }
    __syncwarp();  // S0 (in Fs) visible to all threads of the point

    // ===== peel step 0 =====
    mm4z<16>(W, T, Fs);                          // W = P * S0
    KICK();                                      // kick1
    st4(Ws, W, q);                               // stash W
    E_SECTION();                                 // tile = E0, G = E0
    st4(Fs, G, q);                               // F := E0

    // ===== steps 1..3: uniform, branch-free =====
#pragma unroll 1
    for (int step = 1; step < NSTEPS; step++) {
        ld4(T, Ws, q);                           // W_old
        mm4z<TSTR>(W, T, tile);                  // W <- W_old * E_prev
        KICK();                                  // kick2 of prev step
        KICK();                                  // kick1 of this step
        st4(Ws, W, q);                           // stash W
        E_SECTION();                             // tile = E_step
        ld4(T, Fs, q);                           // F
        mm4z<TSTR>(G, T, tile);                  // F <- F * E_step
        st4(Fs, G, q);
    }

    // ===== final: S_out = sym(S0 * F) =====
#pragma unroll
    for (int r = 0; r < 4; r++)
        ld_row16(T[r], Sigma + (size_t)p * 256 + (q + 4 * r) * 16);
    __syncwarp();                                // all F rows written
    mm4z<16>(W, T, Fs);                          // W = S0 * F
    put4(tile, q, W);                            // tile <- S_new (transpose)
#pragma unroll
    for (int r = 0; r < 4; r++) {
#pragma unroll
        for (int j = 0; j < 16; j++)
            W[r][j] = 0.5f * (W[r][j] + tile[j * TSTR + q + 4 * r]);
        st_row16(Sig_o + (size_t)p * 256 + (q + 4 * r) * 16, W[r]);
    }
}

extern "C" void kernel_launch(void* const* d_in, const int* in_sizes, int n_in,
                              void* d_out, int out_size) {
    const float* mu       = (const float*)d_in[0];
    const float* Sigma    = (const float*)d_in[1];
    const float* phi      = (const float*)d_in[2];
    const float* pi_mu    = (const float*)d_in[3];
    const float* pi_Sigma = (const float*)d_in[4];
    const float* pi_phi   = (const float*)d_in[5];
    const float* M_inv    = (const float*)d_in[6];

    const int npts = in_sizes[0] / 16;  // B*N = 32768
    float* out = (float*)d_out;
    float* mu_o  = out;
    float* Sig_o = out + (size_t)npts * 16;
    float* phi_o = out + (size_t)npts * 16 + (size_t)npts * 256;

    cudaFuncSetAttribute(ham_kernel, cudaFuncAttributeMaxDynamicSharedMemorySize,
                         SMEM_BYTES);

    dim3 grid(npts / PTS);
    dim3 block(NTHREADS);
    ham_kernel<<<grid, block, SMEM_BYTES>>>(mu, Sigma, phi, pi_mu, pi_Sigma,
                                            pi_phi, M_inv, mu_o, Sig_o, phi_o);
}

// round 16
// speedup vs baseline: 1.1461x; 1.1415x over previous
#include <cuda_runtime.h>
#include <math.h>

#define DT 0.05f
#define NSTEPS 4
#define NTHREADS 128
#define PTS 16          // points per block (8 threads each)
#define TSTR 20         // tile row stride (floats): conflict-free, 16B aligned
#define PPB 580         // tile 320 + Fs 256 + pad (mod 32 == 4)
#define TILE_OFF 0
#define F_OFF 320       // S0 initially, then F accumulator
#define SMEM_BYTES (PTS * PPB * 4)

typedef unsigned long long u64;

__device__ __forceinline__ u64 pack2(float x, float y) {
    u64 r;
    asm("mov.b64 %0, {%1, %2};" : "=l"(r) : "f"(x), "f"(y));
    return r;
}
__device__ __forceinline__ void unpack2(u64 v, float& x, float& y) {
    asm("mov.b64 {%0, %1}, %2;" : "=f"(x), "=f"(y) : "l"(v));
}
__device__ __forceinline__ void fma2(u64& d, u64 a, u64 b) {
    asm("fma.rn.f32x2 %0, %1, %2, %0;" : "+l"(d) : "l"(a), "l"(b));
}

__device__ __forceinline__ void put2(float* tile, int q, const float v0[16],
                                     const float v1[16]) {
    __syncwarp();
    float4* d0 = (float4*)(tile + q * TSTR);
    float4* d1 = (float4*)(tile + (q + 8) * TSTR);
    d0[0] = make_float4(v0[0], v0[1], v0[2], v0[3]);
    d0[1] = make_float4(v0[4], v0[5], v0[6], v0[7]);
    d0[2] = make_float4(v0[8], v0[9], v0[10], v0[11]);
    d0[3] = make_float4(v0[12], v0[13], v0[14], v0[15]);
    d1[0] = make_float4(v1[0], v1[1], v1[2], v1[3]);
    d1[1] = make_float4(v1[4], v1[5], v1[6], v1[7]);
    d1[2] = make_float4(v1[8], v1[9], v1[10], v1[11]);
    d1[3] = make_float4(v1[12], v1[13], v1[14], v1[15]);
    __syncwarp();
}

// c{0,1} = a{0,1} * B. c, a distinct arrays.
template <int BSTR>
__device__ __forceinline__ void mm2z(float c0[16], float c1[16],
                                     const float a0[16], const float a1[16],
                                     const float* Bs) {
    u64 acc0[8], acc1[8];
#pragma unroll
    for (int i = 0; i < 8; i++) { acc0[i] = 0ULL; acc1[i] = 0ULL; }
#pragma unroll
    for (int k = 0; k < 16; k++) {
        const ulonglong2* bp = (const ulonglong2*)(Bs + k * BSTR);
        ulonglong2 ba = bp[0], bb = bp[1], bc = bp[2], bd = bp[3];
        u64 ak0 = pack2(a0[k], a0[k]);
        u64 ak1 = pack2(a1[k], a1[k]);
        fma2(acc0[0], ak0, ba.x); fma2(acc0[1], ak0, ba.y);
        fma2(acc0[2], ak0, bb.x); fma2(acc0[3], ak0, bb.y);
        fma2(acc0[4], ak0, bc.x); fma2(acc0[5], ak0, bc.y);
        fma2(acc0[6], ak0, bd.x); fma2(acc0[7], ak0, bd.y);
        fma2(acc1[0], ak1, ba.x); fma2(acc1[1], ak1, ba.y);
        fma2(acc1[2], ak1, bb.x); fma2(acc1[3], ak1, bb.y);
        fma2(acc1[4], ak1, bc.x); fma2(acc1[5], ak1, bc.y);
        fma2(acc1[6], ak1, bd.x); fma2(acc1[7], ak1, bd.y);
    }
#pragma unroll
    for (int i = 0; i < 8; i++) {
        unpack2(acc0[i], c0[2 * i], c0[2 * i + 1]);
        unpack2(acc1[i], c1[2 * i], c1[2 * i + 1]);
    }
}

// c{0,1} += a{0,1} * B. c, a distinct arrays.
template <int BSTR>
__device__ __forceinline__ void mm2a(float c0[16], float c1[16],
                                     const float a0[16], const float a1[16],
                                     const float* Bs) {
    u64 acc0[8], acc1[8];
#pragma unroll
    for (int i = 0; i < 8; i++) {
        acc0[i] = pack2(c0[2 * i], c0[2 * i + 1]);
        acc1[i] = pack2(c1[2 * i], c1[2 * i + 1]);
    }
#pragma unroll
    for (int k = 0; k < 16; k++) {
        const ulonglong2* bp = (const ulonglong2*)(Bs + k * BSTR);
        ulonglong2 ba = bp[0], bb = bp[1], bc = bp[2], bd = bp[3];
        u64 ak0 = pack2(a0[k], a0[k]);
        u64 ak1 = pack2(a1[k], a1[k]);
        fma2(acc0[0], ak0, ba.x); fma2(acc0[1], ak0, ba.y);
        fma2(acc0[2], ak0, bb.x); fma2(acc0[3], ak0, bb.y);
        fma2(acc0[4], ak0, bc.x); fma2(acc0[5], ak0, bc.y);
        fma2(acc0[6], ak0, bd.x); fma2(acc0[7], ak0, bd.y);
        fma2(acc1[0], ak1, ba.x); fma2(acc1[1], ak1, ba.y);
        fma2(acc1[2], ak1, bb.x); fma2(acc1[3], ak1, bb.y);
        fma2(acc1[4], ak1, bc.x); fma2(acc1[5], ak1, bc.y);
        fma2(acc1[6], ak1, bd.x); fma2(acc1[7], ak1, bd.y);
    }
#pragma unroll
    for (int i = 0; i < 8; i++) {
        unpack2(acc0[i], c0[2 * i], c0[2 * i + 1]);
        unpack2(acc1[i], c1[2 * i], c1[2 * i + 1]);
    }
}

__device__ __forceinline__ void ld_row16(float v[16], const float* src) {
    const float4* s = (const float4*)src;
#pragma unroll
    for (int i = 0; i < 4; i++) {
        float4 t = s[i];
        v[4 * i + 0] = t.x; v[4 * i + 1] = t.y;
        v[4 * i + 2] = t.z; v[4 * i + 3] = t.w;
    }
}
__device__ __forceinline__ void st_row16(float* dst, const float v[16]) {
    float4* d = (float4*)dst;
    d[0] = make_float4(v[0], v[1], v[2], v[3]);
    d[1] = make_float4(v[4], v[5], v[6], v[7]);
    d[2] = make_float4(v[8], v[9], v[10], v[11]);
    d[3] = make_float4(v[12], v[13], v[14], v[15]);
}

// kick: W <- W - dt*W^2   (live: W, T, acc)
#define KICK()                                                               \
    do {                                                                     \
        put2(tile, q, W0, W1);                                               \
        _Pragma("unroll")                                                    \
        for (int j = 0; j < 16; j++) { T0[j] = -DT * W0[j]; T1[j] = -DT * W1[j]; } \
        mm2a<TSTR>(W0, W1, T0, T1, tile);                                    \
    } while (0)

// E-section: direct deg-4 Taylor on X = 2dt*W (no squaring).
// E = (I+X) + X^2*(1/2 I + 1/6 X + 1/24 X^2).  Error ~ ||X||^5/120 ~ 5e-5.
// Entry: W regs = W (PRESERVED — fits in 255-reg budget, ~190 live max).
// Exit: tile = E, T = E.  Uses 2 matmuls.
#define E_SECTION()                                                          \
    do {                                                                     \
        _Pragma("unroll")                                                    \
        for (int j = 0; j < 16; j++) {                                       \
            T0[j] = 2.0f * DT * W0[j]; T1[j] = 2.0f * DT * W1[j];            \
        }                                                                    \
        put2(tile, q, T0, T1);                   /* tile <- X */             \
        mm2z<TSTR>(G0, G1, T0, T1, tile);        /* G = X^2 */               \
        _Pragma("unroll")                                                    \
        for (int j = 0; j < 16; j++) {                                       \
            T0[j] = fmaf(1.0f / 24.0f, G0[j], (1.0f / 6.0f) * T0[j]);        \
            T1[j] = fmaf(1.0f / 24.0f, G1[j], (1.0f / 6.0f) * T1[j]);        \
        }                                                                    \
        T0[q] += 0.5f; T1[r1] += 0.5f;           /* T = U */                 \
        put2(tile, q, T0, T1);                   /* tile <- U */             \
        _Pragma("unroll")                                                    \
        for (int j = 0; j < 16; j++) {                                       \
            T0[j] = 2.0f * DT * W0[j]; T1[j] = 2.0f * DT * W1[j];            \
        }                                                                    \
        T0[q] += 1.0f; T1[r1] += 1.0f;           /* T = I + X */             \
        mm2a<TSTR>(T0, T1, G0, G1, tile);        /* T = E */                 \
        put2(tile, q, T0, T1);                   /* tile <- E */             \
    } while (0)

__global__ void __launch_bounds__(NTHREADS, 2)
ham_kernel(const float* __restrict__ mu, const float* __restrict__ Sigma,
           const float* __restrict__ phi, const float* __restrict__ pi_mu,
           const float* __restrict__ pi_Sigma, const float* __restrict__ pi_phi,
           const float* __restrict__ M_inv,
           float* __restrict__ mu_o, float* __restrict__ Sig_o,
           float* __restrict__ phi_o) {
    extern __shared__ float smem[];
    const int tid = threadIdx.x;
    const int lp = tid >> 3;   // local point 0..15
    const int q = tid & 7;     // owns rows q and q+8
    const int r1 = q + 8;
    const int p = blockIdx.x * PTS + lp;
    float* tile = smem + lp * PPB + TILE_OFF;
    float* Fs = smem + lp * PPB + F_OFF;   // stride 16

    float W0[16], W1[16], T0[16], T1[16], G0[16], G1[16];

    // ---- S0 -> Fs (temporary home); P -> T ----
    ld_row16(T0, Sigma + (size_t)p * 256 + q * 16);
    ld_row16(T1, Sigma + (size_t)p * 256 + r1 * 16);
    st_row16(Fs + q * 16, T0);
    st_row16(Fs + r1 * 16, T1);
    ld_row16(T0, pi_Sigma + (size_t)p * 256 + q * 16);
    ld_row16(T1, pi_Sigma + (size_t)p * 256 + r1 * 16);

    // ---- mu update: mu + NSTEPS*dt * M_inv @ pi_mu ----
    {
        float pmv[16];
        ld_row16(pmv, pi_mu + (size_t)p * 16);
        const float* M0 = M_inv + (size_t)p * 256 + q * 16;
        const float* M1 = M_inv + (size_t)p * 256 + r1 * 16;
        float s0 = 0.0f, s1 = 0.0f;
#pragma unroll
        for (int j = 0; j < 16; j++) {
            s0 = fmaf(M0[j], pmv[j], s0);
            s1 = fmaf(M1[j], pmv[j], s1);
        }
        mu_o[(size_t)p * 16 + q]  = mu[(size_t)p * 16 + q]  + ((float)NSTEPS * DT) * s0;
        mu_o[(size_t)p * 16 + r1] = mu[(size_t)p * 16 + r1] + ((float)NSTEPS * DT) * s1;
    }

    // ---- phi update (thread q==0 of each point) ----
    if (q == 0) {
        float px = phi[p * 3 + 0], py = phi[p * 3 + 1], pz = phi[p * 3 + 2];
        const float vx = pi_phi[p * 3 + 0];
        const float vy = pi_phi[p * 3 + 1];
        const float vz = pi_phi[p * 3 + 2];
        const float TWO_PI = 6.283185307179586f;
        const float PI_F = 3.141592653589793f;
        const float R_MAX = 3.131592653589793f;
#pragma unroll 1
        for (int s = 0; s < NSTEPS; s++) {
            px += DT * vx; py += DT * vy; pz += DT * vz;
            float th = sqrtf(px * px + py * py + pz * pz);
            float ths = fmaxf(th, 1e-12f);
            float inv = 1.0f / ths;
            float ax = px * inv, ay = py * inv, az = pz * inv;
            float tw = fmodf(th, TWO_PI);
            bool flip = tw > PI_F;
            float tf = flip ? (TWO_PI - tw) : tw;
            if (flip) { ax = -ax; ay = -ay; az = -az; }
            tf = fminf(tf, R_MAX);
            px = ax * tf; py = ay * tf; pz = az * tf;
        }
        phi_o[p * 3 + 0] = px;
        phi_o[p * 3 + 1] = py;
        phi_o[p * 3 + 2] = pz;
    }
    __syncwarp();  // S0 (in Fs) visible to all threads of the point

    // ===== peel step 0: W = P*S0 ; kick ; E0 ; F := E0 =====
    mm2z<16>(W0, W1, T0, T1, Fs);                // W = P * S0
    KICK();                                      // kick1
    E_SECTION();                                 // tile = E0, T = E0; W live
    st_row16(Fs + q * 16, T0);                   // F := E0 (own rows)
    st_row16(Fs + r1 * 16, T1);

    // ===== steps 1..3: uniform, branch-free; W stays in registers =====
#pragma unroll 1
    for (int step = 1; step < NSTEPS; step++) {
        mm2z<TSTR>(G0, G1, W0, W1, tile);        // G = W * E_prev
#pragma unroll
        for (int j = 0; j < 16; j++) { W0[j] = G0[j]; W1[j] = G1[j]; }
        KICK();                                  // kick2 of prev step
        KICK();                                  // kick1 of this step
        E_SECTION();                             // tile = E_step, T = E; W live
        ld_row16(G0, Fs + q * 16);               // G = F rows (own)
        ld_row16(G1, Fs + r1 * 16);
        mm2z<TSTR>(T0, T1, G0, G1, tile);        // T = F * E_step
        st_row16(Fs + q * 16, T0);
        st_row16(Fs + r1 * 16, T1);
    }

    // ===== final: S_out = sym(S0 * F) =====
    ld_row16(T0, Sigma + (size_t)p * 256 + q * 16);   // S0 rows (L2)
    ld_row16(T1, Sigma + (size_t)p * 256 + r1 * 16);
    __syncwarp();                                // all F rows written
    mm2z<16>(W0, W1, T0, T1, Fs);                // W = S0 * F
    put2(tile, q, W0, W1);                       // tile <- S_new (transpose)
#pragma unroll
    for (int j = 0; j < 16; j++) {
        W0[j] = 0.5f * (W0[j] + tile[j * TSTR + q]);
        W1[j] = 0.5f * (W1[j] + tile[j * TSTR + r1]);
    }
    st_row16(Sig_o + (size_t)p * 256 + q * 16, W0);
    st_row16(Sig_o + (size_t)p * 256 + r1 * 16, W1);
}

extern "C" void kernel_launch(void* const* d_in, const int* in_sizes, int n_in,
                              void* d_out, int out_size) {
    const float* mu       = (const float*)d_in[0];
    const float* Sigma    = (const float*)d_in[1];
    const float* phi      = (const float*)d_in[2];
    const float* pi_mu    = (const float*)d_in[3];
    const float* pi_Sigma = (const float*)d_in[4];
    const float* pi_phi   = (const float*)d_in[5];
    const float* M_inv    = (const float*)d_in[6];

    const int npts = in_sizes[0] / 16;  // B*N = 32768
    float* out = (float*)d_out;
    float* mu_o  = out;
    float* Sig_o = out + (size_t)npts * 16;
    float* phi_o = out + (size_t)npts * 16 + (size_t)npts * 256;

    cudaFuncSetAttribute(ham_kernel, cudaFuncAttributeMaxDynamicSharedMemorySize,
                         SMEM_BYTES);

    dim3 grid(npts / PTS);
    dim3 block(NTHREADS);
    ham_kernel<<<grid, block, SMEM_BYTES>>>(mu, Sigma, phi, pi_mu, pi_Sigma,
                                            pi_phi, M_inv, mu_o, Sig_o, phi_o);
}

// round 17
// speedup vs baseline: 1.2380x; 1.0802x over previous
#include <cuda_runtime.h>
#include <math.h>

#define DT 0.05f
#define NSTEPS 4
#define NTHREADS 256
#define PTS 8           // points per block; 1 warp == 1 point (32 thr/point)
#define TSTR 20         // row stride (floats) for tile AND Fs: conflict-free
#define PPB 656         // tile 320 + Fs 320 + pad 16
#define SMEM_BYTES (PTS * PPB * 4)

typedef unsigned long long u64;

__device__ __forceinline__ u64 pack2(float x, float y) {
    u64 r;
    asm("mov.b64 %0, {%1, %2};" : "=l"(r) : "f"(x), "f"(y));
    return r;
}
__device__ __forceinline__ void unpack2(u64 v, float& x, float& y) {
    asm("mov.b64 {%0, %1}, %2;" : "=f"(x), "=f"(y) : "l"(v));
}
__device__ __forceinline__ void fma2(u64& d, u64 a, u64 b) {
    asm("fma.rn.f32x2 %0, %1, %2, %0;" : "+l"(d) : "l"(a), "l"(b));
}

// Each thread owns 8 floats: row r, columns [h*8, h*8+8).
__device__ __forceinline__ void st8s(float* dst, const float v[8]) {
    float4* d = (float4*)dst;
    d[0] = make_float4(v[0], v[1], v[2], v[3]);
    d[1] = make_float4(v[4], v[5], v[6], v[7]);
}
__device__ __forceinline__ void ld8s(float v[8], const float* src) {
    float4 a = ((const float4*)src)[0];
    float4 b = ((const float4*)src)[1];
    v[0] = a.x; v[1] = a.y; v[2] = a.z; v[3] = a.w;
    v[4] = b.x; v[5] = b.y; v[6] = b.z; v[7] = b.w;
}

// Publish this thread's half-row to the tile (warp-fenced both sides).
__device__ __forceinline__ void put8(float* tile, int tbase, const float v[8]) {
    __syncwarp();
    st8s(tile + tbase, v);
    __syncwarp();
}

// Build the full 16-float A-row from own half + partner's half (lane^1).
// Compile-time indices only (runtime indexing would demote to local mem).
__device__ __forceinline__ void build_af(float af[16], const float a[8], int h) {
#pragma unroll
    for (int i = 0; i < 8; i++) {
        float other = __shfl_xor_sync(0xffffffffu, a[i], 1);
        float own = a[i];
        af[i]     = h ? other : own;
        af[i + 8] = h ? own : other;
    }
}

// c = a_row * B   (zero-init). B rows at stride TSTR in shared.
__device__ __forceinline__ void mmz8(float c[8], const float a[8],
                                     const float* Bs, int h) {
    float af[16];
    build_af(af, a, h);
    u64 acc[4];
#pragma unroll
    for (int i = 0; i < 4; i++) acc[i] = 0ULL;
#pragma unroll
    for (int k = 0; k < 16; k++) {
        const ulonglong2* bp = (const ulonglong2*)(Bs + k * TSTR + (h << 3));
        ulonglong2 bA = bp[0];
        ulonglong2 bB = bp[1];
        u64 ak = pack2(af[k], af[k]);
        fma2(acc[0], ak, bA.x); fma2(acc[1], ak, bA.y);
        fma2(acc[2], ak, bB.x); fma2(acc[3], ak, bB.y);
    }
#pragma unroll
    for (int i = 0; i < 4; i++) unpack2(acc[i], c[2 * i], c[2 * i + 1]);
}

// c += a_row * B
__device__ __forceinline__ void mma8(float c[8], const float a[8],
                                     const float* Bs, int h) {
    float af[16];
    build_af(af, a, h);
    u64 acc[4];
#pragma unroll
    for (int i = 0; i < 4; i++) acc[i] = pack2(c[2 * i], c[2 * i + 1]);
#pragma unroll
    for (int k = 0; k < 16; k++) {
        const ulonglong2* bp = (const ulonglong2*)(Bs + k * TSTR + (h << 3));
        ulonglong2 bA = bp[0];
        ulonglong2 bB = bp[1];
        u64 ak = pack2(af[k], af[k]);
        fma2(acc[0], ak, bA.x); fma2(acc[1], ak, bA.y);
        fma2(acc[2], ak, bB.x); fma2(acc[3], ak, bB.y);
    }
#pragma unroll
    for (int i = 0; i < 4; i++) unpack2(acc[i], c[2 * i], c[2 * i + 1]);
}

// Add val to the diagonal element if it falls in this thread's columns.
#define DIAG_ADD(A, val)                                                     \
    do {                                                                     \
        _Pragma("unroll")                                                    \
        for (int i = 0; i < 8; i++)                                          \
            A[i] += (cbase + i == r) ? (val) : 0.0f;                         \
    } while (0)

// kick: W <- W - dt*W^2
#define KICK()                                                               \
    do {                                                                     \
        put8(tile, tbase, W);                                                \
        _Pragma("unroll")                                                    \
        for (int j = 0; j < 8; j++) T[j] = -DT * W[j];                       \
        mma8(W, T, tile, h);                                                 \
    } while (0)

// E-section: direct deg-4 Taylor on X = 2dt*W.
// E = (I+X) + X^2*(1/2 I + 1/6 X + 1/24 X^2). W preserved. Exit: tile=E, T=E.
#define E_SECTION()                                                          \
    do {                                                                     \
        _Pragma("unroll")                                                    \
        for (int j = 0; j < 8; j++) T[j] = 2.0f * DT * W[j];                 \
        put8(tile, tbase, T);                    /* tile <- X */             \
        mmz8(G, T, tile, h);                     /* G = X^2 */               \
        _Pragma("unroll")                                                    \
        for (int j = 0; j < 8; j++)                                          \
            T[j] = fmaf(1.0f / 24.0f, G[j], (1.0f / 6.0f) * T[j]);           \
        DIAG_ADD(T, 0.5f);                                                   \
        put8(tile, tbase, T);                    /* tile <- U */             \
        _Pragma("unroll")                                                    \
        for (int j = 0; j < 8; j++) T[j] = 2.0f * DT * W[j];                 \
        DIAG_ADD(T, 1.0f);                       /* T = I + X */             \
        mma8(T, G, tile, h);                     /* T = E */                 \
        put8(tile, tbase, T);                    /* tile <- E */             \
    } while (0)

__global__ void __launch_bounds__(NTHREADS, 2)
ham_kernel(const float* __restrict__ mu, const float* __restrict__ Sigma,
           const float* __restrict__ phi, const float* __restrict__ pi_mu,
           const float* __restrict__ pi_Sigma, const float* __restrict__ pi_phi,
           const float* __restrict__ M_inv,
           float* __restrict__ mu_o, float* __restrict__ Sig_o,
           float* __restrict__ phi_o) {
    extern __shared__ float smem[];
    const int tid = threadIdx.x;
    const int lp = tid >> 5;         // local point 0..7 (warp id)
    const int lane = tid & 31;
    const int r = lane >> 1;         // row 0..15
    const int h = lane & 1;          // half 0..1
    const int cbase = h << 3;        // first column owned
    const int p = blockIdx.x * PTS + lp;
    float* tile = smem + lp * PPB;          // 16 x TSTR
    float* Fs = tile + 320;                 // 16 x TSTR

    const int tbase = r * TSTR + cbase;     // this thread's slot in tile/Fs
    const size_t mat = (size_t)p * 256 + r * 16 + cbase;

    float W[8], T[8], G[8];

    // ---- S0 -> Fs; P -> T ----
    ld8s(T, Sigma + mat);
    st8s(Fs + tbase, T);
    ld8s(T, pi_Sigma + mat);

    // ---- mu update (h==0 threads, one row each) ----
    if (h == 0) {
        const float* pm = pi_mu + (size_t)p * 16;
        const float* Mr = M_inv + (size_t)p * 256 + r * 16;
        float s = 0.0f;
#pragma unroll
        for (int j = 0; j < 16; j++) s = fmaf(Mr[j], pm[j], s);
        mu_o[(size_t)p * 16 + r] =
            mu[(size_t)p * 16 + r] + ((float)NSTEPS * DT) * s;
    }

    // ---- phi update (lane 0 of each point) ----
    if (lane == 0) {
        float px = phi[p * 3 + 0], py = phi[p * 3 + 1], pz = phi[p * 3 + 2];
        const float vx = pi_phi[p * 3 + 0];
        const float vy = pi_phi[p * 3 + 1];
        const float vz = pi_phi[p * 3 + 2];
        const float TWO_PI = 6.283185307179586f;
        const float PI_F = 3.141592653589793f;
        const float R_MAX = 3.131592653589793f;
#pragma unroll 1
        for (int s = 0; s < NSTEPS; s++) {
            px += DT * vx; py += DT * vy; pz += DT * vz;
            float th = sqrtf(px * px + py * py + pz * pz);
            float ths = fmaxf(th, 1e-12f);
            float inv = 1.0f / ths;
            float ax = px * inv, ay = py * inv, az = pz * inv;
            float tw = fmodf(th, TWO_PI);
            bool flip = tw > PI_F;
            float tf = flip ? (TWO_PI - tw) : tw;
            if (flip) { ax = -ax; ay = -ay; az = -az; }
            tf = fminf(tf, R_MAX);
            px = ax * tf; py = ay * tf; pz = az * tf;
        }
        phi_o[p * 3 + 0] = px;
        phi_o[p * 3 + 1] = py;
        phi_o[p * 3 + 2] = pz;
    }
    __syncwarp();   // S0 (in Fs) visible to the whole warp (= point)

    // ===== peel step 0: W = P*S0 ; kick ; E0 ; F := E0 =====
    mmz8(W, T, Fs, h);                           // W = P * S0
    KICK();                                      // kick1
    E_SECTION();                                 // tile = E0, T = E0
    st8s(Fs + tbase, T);                         // F := E0 (own slot)

    // ===== steps 1..3: uniform, branch-free; W stays in registers =====
#pragma unroll 1
    for (int step = 1; step < NSTEPS; step++) {
        mmz8(G, W, tile, h);                     // G = W * E_prev
#pragma unroll
        for (int j = 0; j < 8; j++) W[j] = G[j];
        KICK();                                  // kick2 of prev step
        KICK();                                  // kick1 of this step
        E_SECTION();                             // tile = E_step, T = E
        ld8s(G, Fs + tbase);                     // G = F (own slot)
        mmz8(T, G, tile, h);                     // T = F * E_step
        st8s(Fs + tbase, T);
    }

    // ===== final: S_out = sym(S0 * F) =====
    ld8s(T, Sigma + mat);                        // S0 half-row (L2)
    __syncwarp();                                // all F slots written
    mmz8(W, T, Fs, h);                           // W = S0 * F
    put8(tile, tbase, W);                        // tile <- S_new
#pragma unroll
    for (int i = 0; i < 8; i++)
        W[i] = 0.5f * (W[i] + tile[(cbase + i) * TSTR + r]);
    st8s(Sig_o + mat, W);
}

extern "C" void kernel_launch(void* const* d_in, const int* in_sizes, int n_in,
                              void* d_out, int out_size) {
    const float* mu       = (const float*)d_in[0];
    const float* Sigma    = (const float*)d_in[1];
    const float* phi      = (const float*)d_in[2];
    const float* pi_mu    = (const float*)d_in[3];
    const float* pi_Sigma = (const float*)d_in[4];
    const float* pi_phi   = (const float*)d_in[5];
    const float* M_inv    = (const float*)d_in[6];

    const int npts = in_sizes[0] / 16;  // B*N = 32768
    float* out = (float*)d_out;
    float* mu_o  = out;
    float* Sig_o = out + (size_t)npts * 16;
    float* phi_o = out + (size_t)npts * 16 + (size_t)npts * 256;

    cudaFuncSetAttribute(ham_kernel, cudaFuncAttributeMaxDynamicSharedMemorySize,
                         SMEM_BYTES);

    dim3 grid(npts / PTS);
    dim3 block(NTHREADS);
    ham_kernel<<<grid, block, SMEM_BYTES>>>(mu, Sigma, phi, pi_mu, pi_Sigma,
                                            pi_phi, M_inv, mu_o, Sig_o, phi_o);
}